// round 2
// baseline (speedup 1.0000x reference)
#include <cuda_runtime.h>
#include <cuda_bf16.h>
#include <cstdint>

#define NN 40000
#define EE 640000
#define DD 128
#define LN_EPS 1e-5f

// ---------------- device scratch (static, allowed) ----------------
__device__ __align__(16) float g_dinv[NN];      // deg -> dinv in place
__device__ int   g_cnt[NN];
__device__ int   g_rowptr[NN + 1];
__device__ int   g_cursor[NN];
__device__ int   g_col[EE];
__device__ __align__(16) float g_val[EE];
__device__ __align__(16) float g_T1[(size_t)NN * DD];
__device__ __align__(16) float g_T2[(size_t)NN * DD];
__device__ int   g_tile_ctr;

// ---------------- K0: zero init ----------------
__global__ void init_kernel() {
    int i = blockIdx.x * blockDim.x + threadIdx.x;
    if (i < NN) { g_dinv[i] = 0.f; g_cnt[i] = 0; }
    if (i == 0) g_tile_ctr = 0;
}

// ---------------- K1: degree + count histogram ----------------
__global__ void degree_kernel(const int* __restrict__ ei,
                              const float* __restrict__ w) {
    int e = blockIdx.x * blockDim.x + threadIdx.x;
    if (e >= EE) return;
    int r = ei[e];
    if ((unsigned)r < NN) {
        atomicAdd(&g_dinv[r], w[e]);
        atomicAdd(&g_cnt[r], 1);
    }
}

// ---------------- K2: single-block exclusive scan + dinv ----------------
__global__ void scan_kernel() {
    __shared__ int wsum[32];
    __shared__ int s_carry;
    int tid = threadIdx.x, lane = tid & 31, wid = tid >> 5;
    if (tid == 0) s_carry = 0;
    __syncthreads();
    for (int base = 0; base < NN; base += 1024) {
        int i = base + tid;
        int v = (i < NN) ? g_cnt[i] : 0;
        int s = v;
        #pragma unroll
        for (int o = 1; o < 32; o <<= 1) {
            int t = __shfl_up_sync(0xffffffffu, s, o);
            if (lane >= o) s += t;
        }
        if (lane == 31) wsum[wid] = s;
        __syncthreads();
        if (wid == 0) {
            int ws = wsum[lane];
            #pragma unroll
            for (int o = 1; o < 32; o <<= 1) {
                int t = __shfl_up_sync(0xffffffffu, ws, o);
                if (lane >= o) ws += t;
            }
            wsum[lane] = ws;
        }
        __syncthreads();
        int carry = s_carry;
        int incl = s + (wid ? wsum[wid - 1] : 0);
        int excl = carry + incl - v;
        if (i < NN) {
            g_rowptr[i] = excl;
            g_cursor[i] = excl;
            float dg = g_dinv[i];
            g_dinv[i] = (dg > 0.f) ? rsqrtf(dg) : 0.f;
        }
        __syncthreads();
        if (tid == 1023) s_carry = carry + wsum[31];
        __syncthreads();
    }
    if (threadIdx.x == 0) g_rowptr[NN] = s_carry;
}

// ---------------- K3: scatter edges into CSR with normalized values ----------
__global__ void scatter_kernel(const int* __restrict__ ei,
                               const float* __restrict__ w) {
    int e = blockIdx.x * blockDim.x + threadIdx.x;
    if (e >= EE) return;
    int r = ei[e];
    int c = ei[EE + e];
    if ((unsigned)r >= NN || (unsigned)c >= NN) return;
    int pos = atomicAdd(&g_cursor[r], 1);
    g_col[pos] = c;
    g_val[pos] = -g_dinv[r] * w[e] * g_dinv[c];
}

// ---------------- K4/K5: SpMM  Y = alpha * (L @ X)  [- Xsub] -------------
// warp per row; lane owns float4 (4 channels)
__global__ void spmm_kernel(const float* __restrict__ X,
                            float* __restrict__ Y,
                            const float* __restrict__ Xsub,
                            float alpha) {
    int gw = (blockIdx.x * blockDim.x + threadIdx.x) >> 5;
    if (gw >= NN) return;
    int lane = threadIdx.x & 31;
    int s = g_rowptr[gw], e2 = g_rowptr[gw + 1];
    const float4* Xv = (const float4*)X;
    float4 acc = make_float4(0.f, 0.f, 0.f, 0.f);
    int j = s;
    for (; j + 1 < e2; j += 2) {
        int c0 = g_col[j], c1 = g_col[j + 1];
        float v0 = g_val[j], v1 = g_val[j + 1];
        float4 x0 = Xv[(size_t)c0 * 32 + lane];
        float4 x1 = Xv[(size_t)c1 * 32 + lane];
        acc.x += v0 * x0.x; acc.y += v0 * x0.y; acc.z += v0 * x0.z; acc.w += v0 * x0.w;
        acc.x += v1 * x1.x; acc.y += v1 * x1.y; acc.z += v1 * x1.z; acc.w += v1 * x1.w;
    }
    if (j < e2) {
        int c0 = g_col[j]; float v0 = g_val[j];
        float4 x0 = Xv[(size_t)c0 * 32 + lane];
        acc.x += v0 * x0.x; acc.y += v0 * x0.y; acc.z += v0 * x0.z; acc.w += v0 * x0.w;
    }
    float4 o;
    if (Xsub) {
        float4 xs = ((const float4*)Xsub)[(size_t)gw * 32 + lane];
        o.x = alpha * acc.x - xs.x;
        o.y = alpha * acc.y - xs.y;
        o.z = alpha * acc.z - xs.z;
        o.w = alpha * acc.w - xs.w;
    } else {
        o.x = alpha * acc.x; o.y = alpha * acc.y;
        o.z = alpha * acc.z; o.w = alpha * acc.w;
    }
    ((float4*)Y)[(size_t)gw * 32 + lane] = o;
}

// ---------------- K6: fused GEMM (3 inputs) + bias + LayerNorm + ReLU -------
// out = x@W0 + T1@W1 + T2@W2 + bias -> LN(channel) * gamma + beta -> relu
#define TILE_R 64
#define NTILES (NN / TILE_R)   // 625
#define GEMM_SMEM (3 * 128 * 128 * 4 + TILE_R * 128 * 4)  // 196608 + 32768 = 229376

__global__ __launch_bounds__(256, 1)
void gemm_ln_kernel(const float* __restrict__ X0,
                    const float* __restrict__ X1,
                    const float* __restrict__ X2,
                    const float* __restrict__ W,
                    const float* __restrict__ bias,
                    const float* __restrict__ gamma,
                    const float* __restrict__ beta,
                    float* __restrict__ out) {
    extern __shared__ float smem[];
    float* sW = smem;                    // [3][128][128]
    float* sA = smem + 3 * 128 * 128;    // [TILE_R][128]
    __shared__ int s_tile;

    int tid = threadIdx.x;
    int tx = tid & 31;   // col group: cols tx*4 .. tx*4+3
    int ty = tid >> 5;   // warp id: rows ty*8 .. ty*8+7 within tile

    // stage all 3 weight matrices once per block
    for (int i = tid; i < 3 * 128 * 128 / 4; i += 256)
        ((float4*)sW)[i] = ((const float4*)W)[i];

    float4 bb = ((const float4*)bias)[tx];
    float4 gg = ((const float4*)gamma)[tx];
    float4 be = ((const float4*)beta)[tx];
    const float* Xs[3] = {X0, X1, X2};
    __syncthreads();

    for (;;) {
        if (tid == 0) s_tile = atomicAdd(&g_tile_ctr, 1);
        __syncthreads();
        int tile = s_tile;
        if (tile >= NTILES) break;
        int row0 = tile * TILE_R;

        float acc[8][4];
        #pragma unroll
        for (int r = 0; r < 8; r++)
            #pragma unroll
            for (int c = 0; c < 4; c++) acc[r][c] = 0.f;

        for (int p = 0; p < 3; p++) {
            __syncthreads();  // protect sA reuse across phases/tiles
            const float* Xp = Xs[p];
            for (int i = tid; i < TILE_R * 32; i += 256) {
                int r = i >> 5, c4 = i & 31;
                ((float4*)sA)[i] =
                    ((const float4*)(Xp + (size_t)(row0 + r) * 128))[c4];
            }
            __syncthreads();
            const float* Wp = sW + p * 128 * 128;
            #pragma unroll 2
            for (int k4 = 0; k4 < 128; k4 += 4) {
                float4 a[8];
                #pragma unroll
                for (int r = 0; r < 8; r++)
                    a[r] = *(const float4*)(sA + (ty * 8 + r) * 128 + k4);
                #pragma unroll
                for (int kk = 0; kk < 4; kk++) {
                    float4 b = *(const float4*)(Wp + (k4 + kk) * 128 + tx * 4);
                    #pragma unroll
                    for (int r = 0; r < 8; r++) {
                        float av = (kk == 0) ? a[r].x : (kk == 1) ? a[r].y
                                 : (kk == 2) ? a[r].z : a[r].w;
                        acc[r][0] += av * b.x;
                        acc[r][1] += av * b.y;
                        acc[r][2] += av * b.z;
                        acc[r][3] += av * b.w;
                    }
                }
            }
        }

        // epilogue: bias + LayerNorm (warp holds full 128-col row) + ReLU
        #pragma unroll
        for (int r = 0; r < 8; r++) {
            float v0 = acc[r][0] + bb.x;
            float v1 = acc[r][1] + bb.y;
            float v2 = acc[r][2] + bb.z;
            float v3 = acc[r][3] + bb.w;
            float s  = v0 + v1 + v2 + v3;
            float s2 = v0 * v0 + v1 * v1 + v2 * v2 + v3 * v3;
            #pragma unroll
            for (int o = 16; o; o >>= 1) {
                s  += __shfl_xor_sync(0xffffffffu, s,  o);
                s2 += __shfl_xor_sync(0xffffffffu, s2, o);
            }
            float mean = s * (1.f / 128.f);
            float var  = s2 * (1.f / 128.f) - mean * mean;
            float inv  = rsqrtf(var + LN_EPS);
            int row = row0 + ty * 8 + r;
            float4 o4;
            o4.x = fmaxf((v0 - mean) * inv * gg.x + be.x, 0.f);
            o4.y = fmaxf((v1 - mean) * inv * gg.y + be.y, 0.f);
            o4.z = fmaxf((v2 - mean) * inv * gg.z + be.z, 0.f);
            o4.w = fmaxf((v3 - mean) * inv * gg.w + be.w, 0.f);
            ((float4*)(out + (size_t)row * 128))[tx] = o4;
        }
        __syncthreads();  // before s_tile is rewritten
    }
}

// ---------------- launch ----------------
extern "C" void kernel_launch(void* const* d_in, const int* in_sizes, int n_in,
                              void* d_out, int out_size) {
    const float* x     = (const float*)d_in[0];       // [N,128]
    const float* ew    = (const float*)d_in[1];       // [E]
    const float* W     = (const float*)d_in[2];       // [3,128,128]
    const float* bias  = (const float*)d_in[3];       // [128]
    const float* gamma = (const float*)d_in[4];       // [128]
    const float* beta  = (const float*)d_in[5];       // [128]
    const int*   ei    = (const int*)d_in[6];         // [2,E] int32
    float* out = (float*)d_out;

    float *T1, *T2;
    cudaGetSymbolAddress((void**)&T1, g_T1);
    cudaGetSymbolAddress((void**)&T2, g_T2);

    cudaFuncSetAttribute(gemm_ln_kernel,
                         cudaFuncAttributeMaxDynamicSharedMemorySize,
                         GEMM_SMEM);

    init_kernel<<<(NN + 255) / 256, 256>>>();
    degree_kernel<<<(EE + 255) / 256, 256>>>(ei, ew);
    scan_kernel<<<1, 1024>>>();
    scatter_kernel<<<(EE + 255) / 256, 256>>>(ei, ew);

    // T1 = L x
    spmm_kernel<<<(NN * 32 + 255) / 256, 256>>>(x, T1, nullptr, 1.0f);
    // T2 = 2 L T1 - x
    spmm_kernel<<<(NN * 32 + 255) / 256, 256>>>(T1, T2, x, 2.0f);

    gemm_ln_kernel<<<152, 256, GEMM_SMEM>>>(x, T1, T2, W, bias, gamma, beta, out);
}

// round 4
// speedup vs baseline: 1.2932x; 1.2932x over previous
#include <cuda_runtime.h>
#include <cuda_bf16.h>
#include <cstdint>

#define NN 40000
#define EE 640000
#define DD 128
#define LN_EPS 1e-5f

// ================= device scratch =================
__device__ __align__(16) float g_dinv[NN];
__device__ int   g_cnt[NN];
__device__ int   g_rowptr[NN + 1];
__device__ int   g_cursor[NN];
__device__ int   g_col[EE];
__device__ __align__(16) float g_val[EE];
__device__ __align__(16) float g_T1[(size_t)NN * DD];
__device__ __align__(16) float g_T2[(size_t)NN * DD];
__device__ int   g_tile_ctr;

// ================= K0: init =================
__global__ void init_kernel() {
    int i = blockIdx.x * blockDim.x + threadIdx.x;
    if (i < NN) { g_dinv[i] = 0.f; g_cnt[i] = 0; }
    if (i == 0) g_tile_ctr = 0;
}

// ================= K1: degree =================
__global__ void degree_kernel(const int* __restrict__ ei,
                              const float* __restrict__ w) {
    int e = blockIdx.x * blockDim.x + threadIdx.x;
    if (e >= EE) return;
    int r = ei[e];
    if ((unsigned)r < NN) {
        atomicAdd(&g_dinv[r], w[e]);
        atomicAdd(&g_cnt[r], 1);
    }
}

// ================= K2: scan =================
__global__ void scan_kernel() {
    __shared__ int wsum[32];
    __shared__ int s_carry;
    int tid = threadIdx.x, lane = tid & 31, wid = tid >> 5;
    if (tid == 0) s_carry = 0;
    __syncthreads();
    for (int base = 0; base < NN; base += 1024) {
        int i = base + tid;
        int v = (i < NN) ? g_cnt[i] : 0;
        int s = v;
        #pragma unroll
        for (int o = 1; o < 32; o <<= 1) {
            int t = __shfl_up_sync(0xffffffffu, s, o);
            if (lane >= o) s += t;
        }
        if (lane == 31) wsum[wid] = s;
        __syncthreads();
        if (wid == 0) {
            int ws = wsum[lane];
            #pragma unroll
            for (int o = 1; o < 32; o <<= 1) {
                int t = __shfl_up_sync(0xffffffffu, ws, o);
                if (lane >= o) ws += t;
            }
            wsum[lane] = ws;
        }
        __syncthreads();
        int carry = s_carry;
        int incl = s + (wid ? wsum[wid - 1] : 0);
        int excl = carry + incl - v;
        if (i < NN) {
            g_rowptr[i] = excl;
            g_cursor[i] = excl;
            float dg = g_dinv[i];
            g_dinv[i] = (dg > 0.f) ? rsqrtf(dg) : 0.f;
        }
        __syncthreads();
        if (tid == 1023) s_carry = carry + wsum[31];
        __syncthreads();
    }
    if (threadIdx.x == 0) g_rowptr[NN] = s_carry;
}

// ================= K3: scatter =================
__global__ void scatter_kernel(const int* __restrict__ ei,
                               const float* __restrict__ w) {
    int e = blockIdx.x * blockDim.x + threadIdx.x;
    if (e >= EE) return;
    int r = ei[e];
    int c = ei[EE + e];
    if ((unsigned)r >= NN || (unsigned)c >= NN) return;
    int pos = atomicAdd(&g_cursor[r], 1);
    g_col[pos] = c;
    g_val[pos] = -g_dinv[r] * w[e] * g_dinv[c];
}

// ================= K4/K5: SpMM =================
__global__ void spmm_kernel(const float* __restrict__ X,
                            float* __restrict__ Y,
                            const float* __restrict__ Xsub,
                            float alpha) {
    int gw = (blockIdx.x * blockDim.x + threadIdx.x) >> 5;
    if (gw >= NN) return;
    int lane = threadIdx.x & 31;
    int s = g_rowptr[gw], e2 = g_rowptr[gw + 1];
    const float4* Xv = (const float4*)X;
    float4 acc = make_float4(0.f, 0.f, 0.f, 0.f);
    int j = s;
    for (; j + 1 < e2; j += 2) {
        int c0 = g_col[j], c1 = g_col[j + 1];
        float v0 = g_val[j], v1 = g_val[j + 1];
        float4 x0 = Xv[(size_t)c0 * 32 + lane];
        float4 x1 = Xv[(size_t)c1 * 32 + lane];
        acc.x += v0 * x0.x; acc.y += v0 * x0.y; acc.z += v0 * x0.z; acc.w += v0 * x0.w;
        acc.x += v1 * x1.x; acc.y += v1 * x1.y; acc.z += v1 * x1.z; acc.w += v1 * x1.w;
    }
    if (j < e2) {
        int c0 = g_col[j]; float v0 = g_val[j];
        float4 x0 = Xv[(size_t)c0 * 32 + lane];
        acc.x += v0 * x0.x; acc.y += v0 * x0.y; acc.z += v0 * x0.z; acc.w += v0 * x0.w;
    }
    float4 o;
    if (Xsub) {
        float4 xs = ((const float4*)Xsub)[(size_t)gw * 32 + lane];
        o.x = alpha * acc.x - xs.x;
        o.y = alpha * acc.y - xs.y;
        o.z = alpha * acc.z - xs.z;
        o.w = alpha * acc.w - xs.w;
    } else {
        o.x = alpha * acc.x; o.y = alpha * acc.y;
        o.z = alpha * acc.z; o.w = alpha * acc.w;
    }
    ((float4*)Y)[(size_t)gw * 32 + lane] = o;
}

// ================= K6: mma.sync bf16 GEMM + bias + LN + ReLU =================
// out = x@W0 + T1@W1 + T2@W2 via bf16 hi/lo split -> LN -> ReLU
#define NT 313                          // ceil(40000/128)
#define KPAD 136                        // padded K stride (elements) -> 272B rows
#define MAT_BYTES (128 * KPAD * 2)      // 34816 per bf16 matrix
#define OFF_BIAS  (6 * MAT_BYTES)       // 208896
#define OFF_GAMMA (OFF_BIAS + 512)
#define OFF_BETA  (OFF_GAMMA + 512)
#define GEMM_SMEM (OFF_BETA + 512)      // 210432

__device__ __forceinline__ void mma_bf16(float* c, const uint32_t* a,
                                         uint32_t b0, uint32_t b1) {
    asm volatile(
        "mma.sync.aligned.m16n8k16.row.col.f32.bf16.bf16.f32 "
        "{%0,%1,%2,%3}, {%4,%5,%6,%7}, {%8,%9}, {%0,%1,%2,%3};"
        : "+f"(c[0]), "+f"(c[1]), "+f"(c[2]), "+f"(c[3])
        : "r"(a[0]), "r"(a[1]), "r"(a[2]), "r"(a[3]), "r"(b0), "r"(b1));
}

__device__ __forceinline__ void split2(float x, float y,
                                       uint32_t& hi, uint32_t& lo) {
    __nv_bfloat16 hx = __float2bfloat16(x);
    __nv_bfloat16 hy = __float2bfloat16(y);
    float lx = x - __bfloat162float(hx);
    float ly = y - __bfloat162float(hy);
    __nv_bfloat162 h = __halves2bfloat162(hx, hy);
    __nv_bfloat162 l = __halves2bfloat162(__float2bfloat16(lx),
                                          __float2bfloat16(ly));
    hi = *reinterpret_cast<uint32_t*>(&h);
    lo = *reinterpret_cast<uint32_t*>(&l);
}

__global__ __launch_bounds__(256, 1)
void gemm_mma_kernel(const float* __restrict__ X0,
                     const float* __restrict__ X1,
                     const float* __restrict__ X2,
                     const float* __restrict__ W,
                     const float* __restrict__ bias,
                     const float* __restrict__ gamma,
                     const float* __restrict__ beta,
                     float* __restrict__ out) {
    extern __shared__ char smem[];
    __shared__ int s_tile;
    int tid = threadIdx.x;
    int wid = tid >> 5, lane = tid & 31;
    int tig = lane & 3, gid = lane >> 2;

    float* sBias  = (float*)(smem + OFF_BIAS);
    float* sGamma = (float*)(smem + OFF_GAMMA);
    float* sBeta  = (float*)(smem + OFF_BETA);
    if (tid < 128) {
        sBias[tid]  = bias[tid];
        sGamma[tid] = gamma[tid];
        sBeta[tid]  = beta[tid];
    }

    // stage W: transpose to [n][k] (K padded to 136), hi/lo bf16 split.
    // matrix order: (p*2+0)=hi, (p*2+1)=lo
    for (int idx = tid; idx < 3 * 16384; idx += 256) {
        int p = idx >> 14;
        int r = idx & 16383;
        int k = r >> 7, n = r & 127;
        float v = W[idx];
        __nv_bfloat16 h = __float2bfloat16(v);
        __nv_bfloat16 l = __float2bfloat16(v - __bfloat162float(h));
        size_t eoff = ((size_t)n * KPAD + k) * 2;
        *(__nv_bfloat16*)(smem + (p * 2 + 0) * MAT_BYTES + eoff) = h;
        *(__nv_bfloat16*)(smem + (p * 2 + 1) * MAT_BYTES + eoff) = l;
    }
    __syncthreads();

    const float* Xs[3] = {X0, X1, X2};

    for (;;) {
        if (tid == 0) s_tile = atomicAdd(&g_tile_ctr, 1);
        __syncthreads();
        int tile = s_tile;
        if (tile >= NT) break;
        int row0 = tile * 128;

        int r0 = row0 + wid * 16 + gid;  // rows r0 and r0+8 in this thread
        bool v0 = r0 < NN, v1 = (r0 + 8) < NN;

        float cacc[16][4];
        #pragma unroll
        for (int nt = 0; nt < 16; nt++)
            #pragma unroll
            for (int j = 0; j < 4; j++) cacc[nt][j] = 0.f;

        #pragma unroll 1
        for (int p = 0; p < 3; p++) {
            const float* Xp = Xs[p];
            const char* mhi = smem + (p * 2 + 0) * MAT_BYTES;
            const char* mlo = smem + (p * 2 + 1) * MAT_BYTES;
            #pragma unroll 1
            for (int ks = 0; ks < 8; ks++) {
                int k0 = ks * 16 + tig * 2;
                float2 z = make_float2(0.f, 0.f);
                float2 a00 = v0 ? *(const float2*)(Xp + (size_t)r0 * 128 + k0) : z;
                float2 a10 = v1 ? *(const float2*)(Xp + (size_t)(r0 + 8) * 128 + k0) : z;
                float2 a01 = v0 ? *(const float2*)(Xp + (size_t)r0 * 128 + k0 + 8) : z;
                float2 a11 = v1 ? *(const float2*)(Xp + (size_t)(r0 + 8) * 128 + k0 + 8) : z;
                uint32_t ahi[4], alo[4];
                split2(a00.x, a00.y, ahi[0], alo[0]);
                split2(a10.x, a10.y, ahi[1], alo[1]);
                split2(a01.x, a01.y, ahi[2], alo[2]);
                split2(a11.x, a11.y, ahi[3], alo[3]);

                #pragma unroll
                for (int nt = 0; nt < 16; nt++) {
                    int n = nt * 8 + gid;
                    size_t boff = ((size_t)n * KPAD + ks * 16 + tig * 2) * 2;
                    uint32_t bh0 = *(const uint32_t*)(mhi + boff);
                    uint32_t bh1 = *(const uint32_t*)(mhi + boff + 16);
                    uint32_t bl0 = *(const uint32_t*)(mlo + boff);
                    uint32_t bl1 = *(const uint32_t*)(mlo + boff + 16);
                    mma_bf16(cacc[nt], ahi, bh0, bh1);
                    mma_bf16(cacc[nt], ahi, bl0, bl1);
                    mma_bf16(cacc[nt], alo, bh0, bh1);
                }
            }
        }

        // epilogue: bias + LN (quad reduction) + ReLU + store
        #pragma unroll
        for (int h = 0; h < 2; h++) {
            int r = r0 + h * 8;
            float s1 = 0.f, s2 = 0.f;
            #pragma unroll
            for (int nt = 0; nt < 16; nt++) {
                int col = nt * 8 + tig * 2;
                float a = cacc[nt][2 * h + 0] + sBias[col];
                float b = cacc[nt][2 * h + 1] + sBias[col + 1];
                cacc[nt][2 * h + 0] = a;
                cacc[nt][2 * h + 1] = b;
                s1 += a + b;
                s2 += a * a + b * b;
            }
            s1 += __shfl_xor_sync(0xffffffffu, s1, 1);
            s2 += __shfl_xor_sync(0xffffffffu, s2, 1);
            s1 += __shfl_xor_sync(0xffffffffu, s1, 2);
            s2 += __shfl_xor_sync(0xffffffffu, s2, 2);
            float mean = s1 * (1.f / 128.f);
            float var  = s2 * (1.f / 128.f) - mean * mean;
            float inv  = rsqrtf(var + LN_EPS);
            if (r < NN) {
                #pragma unroll
                for (int nt = 0; nt < 16; nt++) {
                    int col = nt * 8 + tig * 2;
                    float2 o;
                    o.x = fmaxf((cacc[nt][2 * h] - mean) * inv * sGamma[col]
                                + sBeta[col], 0.f);
                    o.y = fmaxf((cacc[nt][2 * h + 1] - mean) * inv * sGamma[col + 1]
                                + sBeta[col + 1], 0.f);
                    *(float2*)(out + (size_t)r * 128 + col) = o;
                }
            }
        }
        __syncthreads();  // protect s_tile rewrite
    }
}

// ================= launch =================
extern "C" void kernel_launch(void* const* d_in, const int* in_sizes, int n_in,
                              void* d_out, int out_size) {
    const float* x     = (const float*)d_in[0];
    const float* ew    = (const float*)d_in[1];
    const float* W     = (const float*)d_in[2];
    const float* bias  = (const float*)d_in[3];
    const float* gamma = (const float*)d_in[4];
    const float* beta  = (const float*)d_in[5];
    const int*   ei    = (const int*)d_in[6];
    float* out = (float*)d_out;

    float *T1, *T2;
    cudaGetSymbolAddress((void**)&T1, g_T1);
    cudaGetSymbolAddress((void**)&T2, g_T2);

    cudaFuncSetAttribute(gemm_mma_kernel,
                         cudaFuncAttributeMaxDynamicSharedMemorySize,
                         GEMM_SMEM);

    init_kernel<<<(NN + 255) / 256, 256>>>();
    degree_kernel<<<(EE + 255) / 256, 256>>>(ei, ew);
    scan_kernel<<<1, 1024>>>();
    scatter_kernel<<<(EE + 255) / 256, 256>>>(ei, ew);

    spmm_kernel<<<(NN * 32 + 255) / 256, 256>>>(x, T1, nullptr, 1.0f);
    spmm_kernel<<<(NN * 32 + 255) / 256, 256>>>(T1, T2, x, 2.0f);

    gemm_mma_kernel<<<148, 256, GEMM_SMEM>>>(x, T1, T2, W, bias, gamma, beta, out);
}

// round 5
// speedup vs baseline: 1.4179x; 1.0964x over previous
#include <cuda_runtime.h>
#include <cuda_bf16.h>
#include <cuda_fp16.h>
#include <cstdint>

#define NN 40000
#define EE 640000
#define DD 128
#define LN_EPS 1e-5f

// ================= device scratch =================
__device__ __align__(16) float g_dinv[NN];
__device__ int   g_cnt[NN];
__device__ int   g_rowptr[NN + 1];
__device__ int   g_cursor[NN];
__device__ int   g_col[EE];
__device__ __align__(16) float g_val[EE];
__device__ __align__(16) float g_T1[(size_t)NN * DD];
__device__ __align__(16) float g_T2[(size_t)NN * DD];
__device__ int   g_tile_ctr;

// ================= K0: init =================
__global__ void init_kernel() {
    int i = blockIdx.x * blockDim.x + threadIdx.x;
    if (i < NN) { g_dinv[i] = 0.f; g_cnt[i] = 0; }
    if (i == 0) g_tile_ctr = 0;
}

// ================= K1: degree =================
__global__ void degree_kernel(const int* __restrict__ ei,
                              const float* __restrict__ w) {
    int e = blockIdx.x * blockDim.x + threadIdx.x;
    if (e >= EE) return;
    int r = ei[e];
    if ((unsigned)r < NN) {
        atomicAdd(&g_dinv[r], w[e]);
        atomicAdd(&g_cnt[r], 1);
    }
}

// ================= K2: scan =================
__global__ void scan_kernel() {
    __shared__ int wsum[32];
    __shared__ int s_carry;
    int tid = threadIdx.x, lane = tid & 31, wid = tid >> 5;
    if (tid == 0) s_carry = 0;
    __syncthreads();
    for (int base = 0; base < NN; base += 1024) {
        int i = base + tid;
        int v = (i < NN) ? g_cnt[i] : 0;
        int s = v;
        #pragma unroll
        for (int o = 1; o < 32; o <<= 1) {
            int t = __shfl_up_sync(0xffffffffu, s, o);
            if (lane >= o) s += t;
        }
        if (lane == 31) wsum[wid] = s;
        __syncthreads();
        if (wid == 0) {
            int ws = wsum[lane];
            #pragma unroll
            for (int o = 1; o < 32; o <<= 1) {
                int t = __shfl_up_sync(0xffffffffu, ws, o);
                if (lane >= o) ws += t;
            }
            wsum[lane] = ws;
        }
        __syncthreads();
        int carry = s_carry;
        int incl = s + (wid ? wsum[wid - 1] : 0);
        int excl = carry + incl - v;
        if (i < NN) {
            g_rowptr[i] = excl;
            g_cursor[i] = excl;
            float dg = g_dinv[i];
            g_dinv[i] = (dg > 0.f) ? rsqrtf(dg) : 0.f;
        }
        __syncthreads();
        if (tid == 1023) s_carry = carry + wsum[31];
        __syncthreads();
    }
    if (threadIdx.x == 0) g_rowptr[NN] = s_carry;
}

// ================= K3: scatter =================
__global__ void scatter_kernel(const int* __restrict__ ei,
                               const float* __restrict__ w) {
    int e = blockIdx.x * blockDim.x + threadIdx.x;
    if (e >= EE) return;
    int r = ei[e];
    int c = ei[EE + e];
    if ((unsigned)r >= NN || (unsigned)c >= NN) return;
    int pos = atomicAdd(&g_cursor[r], 1);
    g_col[pos] = c;
    g_val[pos] = -g_dinv[r] * w[e] * g_dinv[c];
}

// ================= K4/K5: SpMM =================
__global__ void spmm_kernel(const float* __restrict__ X,
                            float* __restrict__ Y,
                            const float* __restrict__ Xsub,
                            float alpha) {
    int gw = (blockIdx.x * blockDim.x + threadIdx.x) >> 5;
    if (gw >= NN) return;
    int lane = threadIdx.x & 31;
    int s = g_rowptr[gw], e2 = g_rowptr[gw + 1];
    const float4* Xv = (const float4*)X;
    float4 acc = make_float4(0.f, 0.f, 0.f, 0.f);
    int j = s;
    for (; j + 1 < e2; j += 2) {
        int c0 = g_col[j], c1 = g_col[j + 1];
        float v0 = g_val[j], v1 = g_val[j + 1];
        float4 x0 = Xv[(size_t)c0 * 32 + lane];
        float4 x1 = Xv[(size_t)c1 * 32 + lane];
        acc.x += v0 * x0.x; acc.y += v0 * x0.y; acc.z += v0 * x0.z; acc.w += v0 * x0.w;
        acc.x += v1 * x1.x; acc.y += v1 * x1.y; acc.z += v1 * x1.z; acc.w += v1 * x1.w;
    }
    if (j < e2) {
        int c0 = g_col[j]; float v0 = g_val[j];
        float4 x0 = Xv[(size_t)c0 * 32 + lane];
        acc.x += v0 * x0.x; acc.y += v0 * x0.y; acc.z += v0 * x0.z; acc.w += v0 * x0.w;
    }
    float4 o;
    if (Xsub) {
        float4 xs = ((const float4*)Xsub)[(size_t)gw * 32 + lane];
        o.x = alpha * acc.x - xs.x;
        o.y = alpha * acc.y - xs.y;
        o.z = alpha * acc.z - xs.z;
        o.w = alpha * acc.w - xs.w;
    } else {
        o.x = alpha * acc.x; o.y = alpha * acc.y;
        o.z = alpha * acc.z; o.w = alpha * acc.w;
    }
    ((float4*)Y)[(size_t)gw * 32 + lane] = o;
}

// ================= K6: fp16 mma GEMM + bias + LN + ReLU =================
// out = x@W0 + T1@W1 + T2@W2 ; A split fp16 hi/lo (exact to 2^-22),
// W single fp16 (err ~2.8e-4 RMS). 2 mmas share one B fragment.
#define NT 313                          // ceil(40000/128)
#define KPAD 136                        // padded K stride (elements) -> 272B rows
#define MAT_BYTES (128 * KPAD * 2)      // 34816 per fp16 matrix
#define OFF_BIAS  (3 * MAT_BYTES)       // 104448
#define OFF_GAMMA (OFF_BIAS + 512)
#define OFF_BETA  (OFF_GAMMA + 512)
#define GEMM_SMEM (OFF_BETA + 512)      // 105984  (x2 CTAs = 211968 <= 228KB)

__device__ __forceinline__ void mma_f16(float* c, const uint32_t* a,
                                        uint32_t b0, uint32_t b1) {
    asm volatile(
        "mma.sync.aligned.m16n8k16.row.col.f32.f16.f16.f32 "
        "{%0,%1,%2,%3}, {%4,%5,%6,%7}, {%8,%9}, {%0,%1,%2,%3};"
        : "+f"(c[0]), "+f"(c[1]), "+f"(c[2]), "+f"(c[3])
        : "r"(a[0]), "r"(a[1]), "r"(a[2]), "r"(a[3]), "r"(b0), "r"(b1));
}

__device__ __forceinline__ void split2h(float x, float y,
                                        uint32_t& hi, uint32_t& lo) {
    __half hx = __float2half_rn(x);
    __half hy = __float2half_rn(y);
    float lx = x - __half2float(hx);
    float ly = y - __half2float(hy);
    __half2 h = __halves2half2(hx, hy);
    __half2 l = __halves2half2(__float2half_rn(lx), __float2half_rn(ly));
    hi = *reinterpret_cast<uint32_t*>(&h);
    lo = *reinterpret_cast<uint32_t*>(&l);
}

__global__ __launch_bounds__(256, 2)
void gemm_mma_kernel(const float* __restrict__ X0,
                     const float* __restrict__ X1,
                     const float* __restrict__ X2,
                     const float* __restrict__ W,
                     const float* __restrict__ bias,
                     const float* __restrict__ gamma,
                     const float* __restrict__ beta,
                     float* __restrict__ out) {
    extern __shared__ char smem[];
    __shared__ int s_tile;
    int tid = threadIdx.x;
    int wid = tid >> 5, lane = tid & 31;
    int tig = lane & 3, gid = lane >> 2;

    float* sBias  = (float*)(smem + OFF_BIAS);
    float* sGamma = (float*)(smem + OFF_GAMMA);
    float* sBeta  = (float*)(smem + OFF_BETA);
    if (tid < 128) {
        sBias[tid]  = bias[tid];
        sGamma[tid] = gamma[tid];
        sBeta[tid]  = beta[tid];
    }

    // stage W: transpose to [n][k] (K padded to 136), fp16
    for (int idx = tid; idx < 3 * 16384; idx += 256) {
        int p = idx >> 14;
        int r = idx & 16383;
        int k = r >> 7, n = r & 127;
        float v = W[idx];
        *(__half*)(smem + p * MAT_BYTES + ((size_t)n * KPAD + k) * 2) =
            __float2half_rn(v);
    }
    __syncthreads();

    const float* Xs[3] = {X0, X1, X2};

    for (;;) {
        if (tid == 0) s_tile = atomicAdd(&g_tile_ctr, 1);
        __syncthreads();
        int tile = s_tile;
        if (tile >= NT) break;
        int row0 = tile * 128;

        int r0 = row0 + wid * 16 + gid;  // rows r0 and r0+8 in this thread
        bool v0 = r0 < NN, v1 = (r0 + 8) < NN;

        float cacc[16][4];
        #pragma unroll
        for (int nt = 0; nt < 16; nt++)
            #pragma unroll
            for (int j = 0; j < 4; j++) cacc[nt][j] = 0.f;

        #pragma unroll 1
        for (int p = 0; p < 3; p++) {
            const float* Xp = Xs[p];
            const char* mw = smem + p * MAT_BYTES;
            #pragma unroll 1
            for (int ks = 0; ks < 8; ks++) {
                int k0 = ks * 16 + tig * 2;
                float2 z = make_float2(0.f, 0.f);
                float2 a00 = v0 ? *(const float2*)(Xp + (size_t)r0 * 128 + k0) : z;
                float2 a10 = v1 ? *(const float2*)(Xp + (size_t)(r0 + 8) * 128 + k0) : z;
                float2 a01 = v0 ? *(const float2*)(Xp + (size_t)r0 * 128 + k0 + 8) : z;
                float2 a11 = v1 ? *(const float2*)(Xp + (size_t)(r0 + 8) * 128 + k0 + 8) : z;
                uint32_t ahi[4], alo[4];
                split2h(a00.x, a00.y, ahi[0], alo[0]);
                split2h(a10.x, a10.y, ahi[1], alo[1]);
                split2h(a01.x, a01.y, ahi[2], alo[2]);
                split2h(a11.x, a11.y, ahi[3], alo[3]);

                #pragma unroll
                for (int nt = 0; nt < 16; nt++) {
                    int n = nt * 8 + gid;
                    size_t boff = ((size_t)n * KPAD + ks * 16 + tig * 2) * 2;
                    uint32_t b0 = *(const uint32_t*)(mw + boff);
                    uint32_t b1 = *(const uint32_t*)(mw + boff + 16);
                    mma_f16(cacc[nt], ahi, b0, b1);
                    mma_f16(cacc[nt], alo, b0, b1);
                }
            }
        }

        // epilogue: bias + LN (quad reduction) + ReLU + store
        #pragma unroll
        for (int h = 0; h < 2; h++) {
            int r = r0 + h * 8;
            float s1 = 0.f, s2 = 0.f;
            #pragma unroll
            for (int nt = 0; nt < 16; nt++) {
                int col = nt * 8 + tig * 2;
                float a = cacc[nt][2 * h + 0] + sBias[col];
                float b = cacc[nt][2 * h + 1] + sBias[col + 1];
                cacc[nt][2 * h + 0] = a;
                cacc[nt][2 * h + 1] = b;
                s1 += a + b;
                s2 += a * a + b * b;
            }
            s1 += __shfl_xor_sync(0xffffffffu, s1, 1);
            s2 += __shfl_xor_sync(0xffffffffu, s2, 1);
            s1 += __shfl_xor_sync(0xffffffffu, s1, 2);
            s2 += __shfl_xor_sync(0xffffffffu, s2, 2);
            float mean = s1 * (1.f / 128.f);
            float var  = s2 * (1.f / 128.f) - mean * mean;
            float inv  = rsqrtf(var + LN_EPS);
            if (r < NN) {
                #pragma unroll
                for (int nt = 0; nt < 16; nt++) {
                    int col = nt * 8 + tig * 2;
                    float2 o;
                    o.x = fmaxf((cacc[nt][2 * h] - mean) * inv * sGamma[col]
                                + sBeta[col], 0.f);
                    o.y = fmaxf((cacc[nt][2 * h + 1] - mean) * inv * sGamma[col + 1]
                                + sBeta[col + 1], 0.f);
                    *(float2*)(out + (size_t)r * 128 + col) = o;
                }
            }
        }
        __syncthreads();  // protect s_tile rewrite
    }
}

// ================= launch =================
extern "C" void kernel_launch(void* const* d_in, const int* in_sizes, int n_in,
                              void* d_out, int out_size) {
    const float* x     = (const float*)d_in[0];
    const float* ew    = (const float*)d_in[1];
    const float* W     = (const float*)d_in[2];
    const float* bias  = (const float*)d_in[3];
    const float* gamma = (const float*)d_in[4];
    const float* beta  = (const float*)d_in[5];
    const int*   ei    = (const int*)d_in[6];
    float* out = (float*)d_out;

    float *T1, *T2;
    cudaGetSymbolAddress((void**)&T1, g_T1);
    cudaGetSymbolAddress((void**)&T2, g_T2);

    cudaFuncSetAttribute(gemm_mma_kernel,
                         cudaFuncAttributeMaxDynamicSharedMemorySize,
                         GEMM_SMEM);

    init_kernel<<<(NN + 255) / 256, 256>>>();
    degree_kernel<<<(EE + 255) / 256, 256>>>(ei, ew);
    scan_kernel<<<1, 1024>>>();
    scatter_kernel<<<(EE + 255) / 256, 256>>>(ei, ew);

    spmm_kernel<<<(NN * 32 + 255) / 256, 256>>>(x, T1, nullptr, 1.0f);
    spmm_kernel<<<(NN * 32 + 255) / 256, 256>>>(T1, T2, x, 2.0f);

    gemm_mma_kernel<<<296, 256, GEMM_SMEM>>>(x, T1, T2, W, bias, gamma, beta, out);
}

// round 6
// speedup vs baseline: 1.4828x; 1.0458x over previous
#include <cuda_runtime.h>
#include <cuda_bf16.h>
#include <cuda_fp16.h>
#include <cstdint>

#define NN 40000
#define EE 640000
#define DD 128
#define LN_EPS 1e-5f

// ================= device scratch =================
__device__ unsigned long long g_deg[NN];          // packed cnt<<44 | fx24
__device__ __align__(16) float g_dinv[NN];
__device__ int   g_rowptr[NN + 1];
__device__ int   g_cursor[NN];
__device__ __align__(16) uint2 g_cv[EE];          // packed {col, val bits}
__device__ __align__(16) float g_T1[(size_t)NN * DD];
__device__ __align__(16) float g_T2[(size_t)NN * DD];
__device__ __align__(16) uint2 g_xh[(size_t)NN * 32];   // x as fp16 (4 halves/uint2)
__device__ __align__(16) uint2 g_t1h[(size_t)NN * 32];  // T1 as fp16
__device__ int   g_tile_ctr;

// ================= K0: convert x -> fp16 + zero init =================
__global__ void convert_init_kernel(const float* __restrict__ x) {
    int i = blockIdx.x * blockDim.x + threadIdx.x;   // one float4 per thread
    if (i < NN * 32) {
        float4 v = ((const float4*)x)[i];
        __half2 a = __floats2half2_rn(v.x, v.y);
        __half2 b = __floats2half2_rn(v.z, v.w);
        uint2 u;
        u.x = *reinterpret_cast<uint32_t*>(&a);
        u.y = *reinterpret_cast<uint32_t*>(&b);
        g_xh[i] = u;
    }
    if (i < NN) g_deg[i] = 0ull;
    if (i == 0) g_tile_ctr = 0;
}

// ================= K1: degree (one packed 64-bit atomic) =================
__global__ void degree_kernel(const int* __restrict__ ei,
                              const float* __restrict__ w) {
    int e = blockIdx.x * blockDim.x + threadIdx.x;
    if (e >= EE) return;
    int r = ei[e];
    if ((unsigned)r < NN) {
        unsigned long long fx =
            (unsigned long long)(w[e] * 16777216.0f);   // w * 2^24
        atomicAdd(&g_deg[r], (1ull << 44) | fx);
    }
}

// ================= K2: scan (counts from packed deg) =================
__global__ void scan_kernel() {
    __shared__ int wsum[32];
    __shared__ int s_carry;
    int tid = threadIdx.x, lane = tid & 31, wid = tid >> 5;
    if (tid == 0) s_carry = 0;
    __syncthreads();
    for (int base = 0; base < NN; base += 1024) {
        int i = base + tid;
        unsigned long long pk = (i < NN) ? g_deg[i] : 0ull;
        int v = (int)(pk >> 44);
        int s = v;
        #pragma unroll
        for (int o = 1; o < 32; o <<= 1) {
            int t = __shfl_up_sync(0xffffffffu, s, o);
            if (lane >= o) s += t;
        }
        if (lane == 31) wsum[wid] = s;
        __syncthreads();
        if (wid == 0) {
            int ws = wsum[lane];
            #pragma unroll
            for (int o = 1; o < 32; o <<= 1) {
                int t = __shfl_up_sync(0xffffffffu, ws, o);
                if (lane >= o) ws += t;
            }
            wsum[lane] = ws;
        }
        __syncthreads();
        int carry = s_carry;
        int incl = s + (wid ? wsum[wid - 1] : 0);
        int excl = carry + incl - v;
        if (i < NN) {
            g_rowptr[i] = excl;
            g_cursor[i] = excl;
            float dg = (float)(pk & ((1ull << 44) - 1)) * 5.9604644775390625e-8f; // *2^-24
            g_dinv[i] = (dg > 0.f) ? rsqrtf(dg) : 0.f;
        }
        __syncthreads();
        if (tid == 1023) s_carry = carry + wsum[31];
        __syncthreads();
    }
    if (threadIdx.x == 0) g_rowptr[NN] = s_carry;
}

// ================= K3: scatter (packed 8B entries) =================
__global__ void scatter_kernel(const int* __restrict__ ei,
                               const float* __restrict__ w) {
    int e = blockIdx.x * blockDim.x + threadIdx.x;
    if (e >= EE) return;
    int r = ei[e];
    int c = ei[EE + e];
    if ((unsigned)r >= NN || (unsigned)c >= NN) return;
    int pos = atomicAdd(&g_cursor[r], 1);
    float val = -g_dinv[r] * w[e] * g_dinv[c];
    uint2 cv;
    cv.x = (uint32_t)c;
    cv.y = __float_as_uint(val);
    g_cv[pos] = cv;
}

// ================= K4/K5: SpMM with fp16 gather =================
// Y = alpha * (L @ Xh) [- Xsub];  optional fp16 mirror Yh of Y
__global__ void spmm_kernel(const uint2* __restrict__ Xh,
                            float* __restrict__ Y,
                            uint2* __restrict__ Yh,
                            const float* __restrict__ Xsub,
                            float alpha) {
    int gw = (blockIdx.x * blockDim.x + threadIdx.x) >> 5;
    if (gw >= NN) return;
    int lane = threadIdx.x & 31;
    int s = g_rowptr[gw], e2 = g_rowptr[gw + 1];
    float4 acc = make_float4(0.f, 0.f, 0.f, 0.f);
    int j = s;
    for (; j + 1 < e2; j += 2) {
        uint2 cv0 = g_cv[j], cv1 = g_cv[j + 1];
        uint2 h0 = Xh[(size_t)cv0.x * 32 + lane];
        uint2 h1 = Xh[(size_t)cv1.x * 32 + lane];
        float v0 = __uint_as_float(cv0.y), v1 = __uint_as_float(cv1.y);
        float2 a0 = __half22float2(*reinterpret_cast<__half2*>(&h0.x));
        float2 b0 = __half22float2(*reinterpret_cast<__half2*>(&h0.y));
        float2 a1 = __half22float2(*reinterpret_cast<__half2*>(&h1.x));
        float2 b1 = __half22float2(*reinterpret_cast<__half2*>(&h1.y));
        acc.x += v0 * a0.x; acc.y += v0 * a0.y; acc.z += v0 * b0.x; acc.w += v0 * b0.y;
        acc.x += v1 * a1.x; acc.y += v1 * a1.y; acc.z += v1 * b1.x; acc.w += v1 * b1.y;
    }
    if (j < e2) {
        uint2 cv0 = g_cv[j];
        uint2 h0 = Xh[(size_t)cv0.x * 32 + lane];
        float v0 = __uint_as_float(cv0.y);
        float2 a0 = __half22float2(*reinterpret_cast<__half2*>(&h0.x));
        float2 b0 = __half22float2(*reinterpret_cast<__half2*>(&h0.y));
        acc.x += v0 * a0.x; acc.y += v0 * a0.y; acc.z += v0 * b0.x; acc.w += v0 * b0.y;
    }
    float4 o;
    if (Xsub) {
        float4 xs = ((const float4*)Xsub)[(size_t)gw * 32 + lane];
        o.x = alpha * acc.x - xs.x;
        o.y = alpha * acc.y - xs.y;
        o.z = alpha * acc.z - xs.z;
        o.w = alpha * acc.w - xs.w;
    } else {
        o.x = alpha * acc.x; o.y = alpha * acc.y;
        o.z = alpha * acc.z; o.w = alpha * acc.w;
    }
    ((float4*)Y)[(size_t)gw * 32 + lane] = o;
    if (Yh) {
        __half2 ha = __floats2half2_rn(o.x, o.y);
        __half2 hb = __floats2half2_rn(o.z, o.w);
        uint2 u;
        u.x = *reinterpret_cast<uint32_t*>(&ha);
        u.y = *reinterpret_cast<uint32_t*>(&hb);
        Yh[(size_t)gw * 32 + lane] = u;
    }
}

// ================= K6: fp16 mma GEMM + bias + LN + ReLU =================
#define NT 313                          // ceil(40000/128)
#define KPAD 136
#define MAT_BYTES (128 * KPAD * 2)      // 34816 per fp16 matrix
#define OFF_BIAS  (3 * MAT_BYTES)
#define OFF_GAMMA (OFF_BIAS + 512)
#define OFF_BETA  (OFF_GAMMA + 512)
#define GEMM_SMEM (OFF_BETA + 512)      // 105984 (x2 CTAs)

__device__ __forceinline__ void mma_f16(float* c, const uint32_t* a,
                                        uint32_t b0, uint32_t b1) {
    asm volatile(
        "mma.sync.aligned.m16n8k16.row.col.f32.f16.f16.f32 "
        "{%0,%1,%2,%3}, {%4,%5,%6,%7}, {%8,%9}, {%0,%1,%2,%3};"
        : "+f"(c[0]), "+f"(c[1]), "+f"(c[2]), "+f"(c[3])
        : "r"(a[0]), "r"(a[1]), "r"(a[2]), "r"(a[3]), "r"(b0), "r"(b1));
}

__device__ __forceinline__ void split2h(float x, float y,
                                        uint32_t& hi, uint32_t& lo) {
    __half hx = __float2half_rn(x);
    __half hy = __float2half_rn(y);
    float lx = x - __half2float(hx);
    float ly = y - __half2float(hy);
    __half2 h = __halves2half2(hx, hy);
    __half2 l = __halves2half2(__float2half_rn(lx), __float2half_rn(ly));
    hi = *reinterpret_cast<uint32_t*>(&h);
    lo = *reinterpret_cast<uint32_t*>(&l);
}

__global__ __launch_bounds__(256, 2)
void gemm_mma_kernel(const float* __restrict__ X0,
                     const float* __restrict__ X1,
                     const float* __restrict__ X2,
                     const float* __restrict__ W,
                     const float* __restrict__ bias,
                     const float* __restrict__ gamma,
                     const float* __restrict__ beta,
                     float* __restrict__ out) {
    extern __shared__ char smem[];
    __shared__ int s_tile;
    int tid = threadIdx.x;
    int wid = tid >> 5, lane = tid & 31;
    int tig = lane & 3, gid = lane >> 2;

    float* sBias  = (float*)(smem + OFF_BIAS);
    float* sGamma = (float*)(smem + OFF_GAMMA);
    float* sBeta  = (float*)(smem + OFF_BETA);
    if (tid < 128) {
        sBias[tid]  = bias[tid];
        sGamma[tid] = gamma[tid];
        sBeta[tid]  = beta[tid];
    }

    for (int idx = tid; idx < 3 * 16384; idx += 256) {
        int p = idx >> 14;
        int r = idx & 16383;
        int k = r >> 7, n = r & 127;
        float v = W[idx];
        *(__half*)(smem + p * MAT_BYTES + ((size_t)n * KPAD + k) * 2) =
            __float2half_rn(v);
    }
    __syncthreads();

    const float* Xs[3] = {X0, X1, X2};

    for (;;) {
        if (tid == 0) s_tile = atomicAdd(&g_tile_ctr, 1);
        __syncthreads();
        int tile = s_tile;
        if (tile >= NT) break;
        int row0 = tile * 128;

        int r0 = row0 + wid * 16 + gid;
        bool v0 = r0 < NN, v1 = (r0 + 8) < NN;

        float cacc[16][4];
        #pragma unroll
        for (int nt = 0; nt < 16; nt++)
            #pragma unroll
            for (int j = 0; j < 4; j++) cacc[nt][j] = 0.f;

        #pragma unroll 1
        for (int p = 0; p < 3; p++) {
            const float* Xp = Xs[p];
            const char* mw = smem + p * MAT_BYTES;
            #pragma unroll 1
            for (int ks = 0; ks < 8; ks++) {
                int k0 = ks * 16 + tig * 2;
                float2 z = make_float2(0.f, 0.f);
                float2 a00 = v0 ? *(const float2*)(Xp + (size_t)r0 * 128 + k0) : z;
                float2 a10 = v1 ? *(const float2*)(Xp + (size_t)(r0 + 8) * 128 + k0) : z;
                float2 a01 = v0 ? *(const float2*)(Xp + (size_t)r0 * 128 + k0 + 8) : z;
                float2 a11 = v1 ? *(const float2*)(Xp + (size_t)(r0 + 8) * 128 + k0 + 8) : z;
                uint32_t ahi[4], alo[4];
                split2h(a00.x, a00.y, ahi[0], alo[0]);
                split2h(a10.x, a10.y, ahi[1], alo[1]);
                split2h(a01.x, a01.y, ahi[2], alo[2]);
                split2h(a11.x, a11.y, ahi[3], alo[3]);

                #pragma unroll
                for (int nt = 0; nt < 16; nt++) {
                    int n = nt * 8 + gid;
                    size_t boff = ((size_t)n * KPAD + ks * 16 + tig * 2) * 2;
                    uint32_t b0 = *(const uint32_t*)(mw + boff);
                    uint32_t b1 = *(const uint32_t*)(mw + boff + 16);
                    mma_f16(cacc[nt], ahi, b0, b1);
                    mma_f16(cacc[nt], alo, b0, b1);
                }
            }
        }

        #pragma unroll
        for (int h = 0; h < 2; h++) {
            int r = r0 + h * 8;
            float s1 = 0.f, s2 = 0.f;
            #pragma unroll
            for (int nt = 0; nt < 16; nt++) {
                int col = nt * 8 + tig * 2;
                float a = cacc[nt][2 * h + 0] + sBias[col];
                float b = cacc[nt][2 * h + 1] + sBias[col + 1];
                cacc[nt][2 * h + 0] = a;
                cacc[nt][2 * h + 1] = b;
                s1 += a + b;
                s2 += a * a + b * b;
            }
            s1 += __shfl_xor_sync(0xffffffffu, s1, 1);
            s2 += __shfl_xor_sync(0xffffffffu, s2, 1);
            s1 += __shfl_xor_sync(0xffffffffu, s1, 2);
            s2 += __shfl_xor_sync(0xffffffffu, s2, 2);
            float mean = s1 * (1.f / 128.f);
            float var  = s2 * (1.f / 128.f) - mean * mean;
            float inv  = rsqrtf(var + LN_EPS);
            if (r < NN) {
                #pragma unroll
                for (int nt = 0; nt < 16; nt++) {
                    int col = nt * 8 + tig * 2;
                    float2 o;
                    o.x = fmaxf((cacc[nt][2 * h] - mean) * inv * sGamma[col]
                                + sBeta[col], 0.f);
                    o.y = fmaxf((cacc[nt][2 * h + 1] - mean) * inv * sGamma[col + 1]
                                + sBeta[col + 1], 0.f);
                    *(float2*)(out + (size_t)r * 128 + col) = o;
                }
            }
        }
        __syncthreads();
    }
}

// ================= launch =================
extern "C" void kernel_launch(void* const* d_in, const int* in_sizes, int n_in,
                              void* d_out, int out_size) {
    const float* x     = (const float*)d_in[0];
    const float* ew    = (const float*)d_in[1];
    const float* W     = (const float*)d_in[2];
    const float* bias  = (const float*)d_in[3];
    const float* gamma = (const float*)d_in[4];
    const float* beta  = (const float*)d_in[5];
    const int*   ei    = (const int*)d_in[6];
    float* out = (float*)d_out;

    float *T1, *T2;
    uint2 *Xh, *T1h;
    cudaGetSymbolAddress((void**)&T1, g_T1);
    cudaGetSymbolAddress((void**)&T2, g_T2);
    cudaGetSymbolAddress((void**)&Xh, g_xh);
    cudaGetSymbolAddress((void**)&T1h, g_t1h);

    cudaFuncSetAttribute(gemm_mma_kernel,
                         cudaFuncAttributeMaxDynamicSharedMemorySize,
                         GEMM_SMEM);

    convert_init_kernel<<<(NN * 32 + 255) / 256, 256>>>(x);
    degree_kernel<<<(EE + 255) / 256, 256>>>(ei, ew);
    scan_kernel<<<1, 1024>>>();
    scatter_kernel<<<(EE + 255) / 256, 256>>>(ei, ew);

    // T1 = L x   (fp16 gather; writes fp32 T1 + fp16 T1h)
    spmm_kernel<<<(NN * 32 + 255) / 256, 256>>>(Xh, T1, T1h, nullptr, 1.0f);
    // T2 = 2 L T1 - x
    spmm_kernel<<<(NN * 32 + 255) / 256, 256>>>(T1h, T2, nullptr, x, 2.0f);

    gemm_mma_kernel<<<296, 256, GEMM_SMEM>>>(x, T1, T2, W, bias, gamma, beta, out);
}

// round 7
// speedup vs baseline: 2.2803x; 1.5378x over previous
#include <cuda_runtime.h>
#include <cuda_bf16.h>
#include <cuda_fp16.h>
#include <cstdint>

#define NN 40000
#define EE 640000
#define DD 128
#define LN_EPS 1e-5f
#define SCAN_BLKS 157   // ceil(40000/256)

// ================= device scratch =================
__device__ unsigned long long g_deg[NN];          // packed cnt<<44 | fx24
__device__ __align__(16) float g_dinv[NN];
__device__ int   g_rowptr[NN + 1];
__device__ int   g_cursor[NN];
__device__ int   g_part[SCAN_BLKS];
__device__ int   g_partscan[SCAN_BLKS];
__device__ __align__(16) uint2 g_cv[EE];          // packed {col, val bits}
__device__ __align__(16) uint2 g_xh[(size_t)NN * 32];   // x fp16
__device__ __align__(16) uint2 g_t1h[(size_t)NN * 32];  // T1 fp16
__device__ __align__(16) uint2 g_t2h[(size_t)NN * 32];  // T2 fp16
__device__ int   g_tile_ctr;

// ================= K1: fused convert(x->fp16) + degree =================
// g_deg assumed zero on entry (zeroed by scan_apply of previous call /
// static zero-init on first call).
__global__ void convert_degree_kernel(const float* __restrict__ x,
                                      const int* __restrict__ ei,
                                      const float* __restrict__ w) {
    int i = blockIdx.x * blockDim.x + threadIdx.x;
    if (i < NN * 32) {
        float4 v = ((const float4*)x)[i];
        __half2 a = __floats2half2_rn(v.x, v.y);
        __half2 b = __floats2half2_rn(v.z, v.w);
        uint2 u;
        u.x = *reinterpret_cast<uint32_t*>(&a);
        u.y = *reinterpret_cast<uint32_t*>(&b);
        g_xh[i] = u;
    }
    if (i < EE) {
        int r = ei[i];
        if ((unsigned)r < NN) {
            unsigned long long fx =
                (unsigned long long)(w[i] * 16777216.0f);   // w * 2^24
            atomicAdd(&g_deg[r], (1ull << 44) | fx);
        }
    }
}

// ================= K2a: per-block count sums =================
__global__ void scan_reduce_kernel() {
    int i = blockIdx.x * 256 + threadIdx.x;
    int v = (i < NN) ? (int)(g_deg[i] >> 44) : 0;
    #pragma unroll
    for (int o = 16; o; o >>= 1) v += __shfl_xor_sync(0xffffffffu, v, o);
    __shared__ int ws[8];
    if ((threadIdx.x & 31) == 0) ws[threadIdx.x >> 5] = v;
    __syncthreads();
    if (threadIdx.x == 0) {
        int s = 0;
        #pragma unroll
        for (int k = 0; k < 8; k++) s += ws[k];
        g_part[blockIdx.x] = s;
    }
}

// ================= K2b: scan the partials (1 block) =================
__global__ void scan_partials_kernel() {
    __shared__ int buf[SCAN_BLKS];
    int tid = threadIdx.x;
    if (tid < SCAN_BLKS) buf[tid] = g_part[tid];
    __syncthreads();
    if (tid == 0) {
        int run = 0;
        for (int k = 0; k < SCAN_BLKS; k++) {
            int t = buf[k];
            buf[k] = run;
            run += t;
        }
        g_rowptr[NN] = run;
    }
    __syncthreads();
    if (tid < SCAN_BLKS) g_partscan[tid] = buf[tid];
}

// ================= K2c: apply scan, dinv, zero deg, reset ctr =================
__global__ void scan_apply_kernel() {
    int i = blockIdx.x * 256 + threadIdx.x;
    int lane = threadIdx.x & 31, wid = threadIdx.x >> 5;
    unsigned long long pk = (i < NN) ? g_deg[i] : 0ull;
    int v = (int)(pk >> 44);
    int s = v;
    #pragma unroll
    for (int o = 1; o < 32; o <<= 1) {
        int t = __shfl_up_sync(0xffffffffu, s, o);
        if (lane >= o) s += t;
    }
    __shared__ int ws[8];
    if (lane == 31) ws[wid] = s;
    __syncthreads();
    if (wid == 0 && lane < 8) {
        int t = ws[lane];
        #pragma unroll
        for (int o = 1; o < 8; o <<= 1) {
            int u = __shfl_up_sync(0xffu, t, o);
            if (lane >= o) t += u;
        }
        ws[lane] = t;
    }
    __syncthreads();
    int excl = s - v + (wid ? ws[wid - 1] : 0) + g_partscan[blockIdx.x];
    if (i < NN) {
        g_rowptr[i] = excl;
        g_cursor[i] = excl;
        float dg = (float)(pk & ((1ull << 44) - 1)) * 5.9604644775390625e-8f;
        g_dinv[i] = (dg > 0.f) ? rsqrtf(dg) : 0.f;
        g_deg[i] = 0ull;            // ready for next replay
    }
    if (i == 0) g_tile_ctr = 0;
}

// ================= K3: scatter (packed 8B entries) =================
__global__ void scatter_kernel(const int* __restrict__ ei,
                               const float* __restrict__ w) {
    int e = blockIdx.x * blockDim.x + threadIdx.x;
    if (e >= EE) return;
    int r = ei[e];
    int c = ei[EE + e];
    if ((unsigned)r >= NN || (unsigned)c >= NN) return;
    int pos = atomicAdd(&g_cursor[r], 1);
    float val = -g_dinv[r] * w[e] * g_dinv[c];
    uint2 cv;
    cv.x = (uint32_t)c;
    cv.y = __float_as_uint(val);
    g_cv[pos] = cv;
}

// ================= K4/K5: SpMM fp16 in / fp16 out =================
// Yh = fp16( alpha * (L @ Xh) [- XsubH] )
__global__ void spmm_kernel(const uint2* __restrict__ Xh,
                            uint2* __restrict__ Yh,
                            const uint2* __restrict__ XsubH,
                            float alpha) {
    int gw = (blockIdx.x * blockDim.x + threadIdx.x) >> 5;
    if (gw >= NN) return;
    int lane = threadIdx.x & 31;
    int s = g_rowptr[gw], e2 = g_rowptr[gw + 1];
    float4 acc = make_float4(0.f, 0.f, 0.f, 0.f);
    int j = s;
    for (; j + 1 < e2; j += 2) {
        uint2 cv0 = g_cv[j], cv1 = g_cv[j + 1];
        uint2 h0 = Xh[(size_t)cv0.x * 32 + lane];
        uint2 h1 = Xh[(size_t)cv1.x * 32 + lane];
        float v0 = __uint_as_float(cv0.y), v1 = __uint_as_float(cv1.y);
        float2 a0 = __half22float2(*reinterpret_cast<__half2*>(&h0.x));
        float2 b0 = __half22float2(*reinterpret_cast<__half2*>(&h0.y));
        float2 a1 = __half22float2(*reinterpret_cast<__half2*>(&h1.x));
        float2 b1 = __half22float2(*reinterpret_cast<__half2*>(&h1.y));
        acc.x += v0 * a0.x; acc.y += v0 * a0.y; acc.z += v0 * b0.x; acc.w += v0 * b0.y;
        acc.x += v1 * a1.x; acc.y += v1 * a1.y; acc.z += v1 * b1.x; acc.w += v1 * b1.y;
    }
    if (j < e2) {
        uint2 cv0 = g_cv[j];
        uint2 h0 = Xh[(size_t)cv0.x * 32 + lane];
        float v0 = __uint_as_float(cv0.y);
        float2 a0 = __half22float2(*reinterpret_cast<__half2*>(&h0.x));
        float2 b0 = __half22float2(*reinterpret_cast<__half2*>(&h0.y));
        acc.x += v0 * a0.x; acc.y += v0 * a0.y; acc.z += v0 * b0.x; acc.w += v0 * b0.y;
    }
    float4 o;
    if (XsubH) {
        uint2 xs = XsubH[(size_t)gw * 32 + lane];
        float2 xa = __half22float2(*reinterpret_cast<__half2*>(&xs.x));
        float2 xb = __half22float2(*reinterpret_cast<__half2*>(&xs.y));
        o.x = alpha * acc.x - xa.x;
        o.y = alpha * acc.y - xa.y;
        o.z = alpha * acc.z - xb.x;
        o.w = alpha * acc.w - xb.y;
    } else {
        o.x = alpha * acc.x; o.y = alpha * acc.y;
        o.z = alpha * acc.z; o.w = alpha * acc.w;
    }
    __half2 ha = __floats2half2_rn(o.x, o.y);
    __half2 hb = __floats2half2_rn(o.z, o.w);
    uint2 u;
    u.x = *reinterpret_cast<uint32_t*>(&ha);
    u.y = *reinterpret_cast<uint32_t*>(&hb);
    Yh[(size_t)gw * 32 + lane] = u;
}

// ================= K6: fp16 mma GEMM + bias + LN + ReLU =================
// out = x@W0 (hi/lo split) + T1h@W1 + T2h@W2 -> LN -> ReLU
#define NT 313
#define KPAD 136
#define MAT_BYTES (128 * KPAD * 2)
#define OFF_BIAS  (3 * MAT_BYTES)
#define OFF_GAMMA (OFF_BIAS + 512)
#define OFF_BETA  (OFF_GAMMA + 512)
#define GEMM_SMEM (OFF_BETA + 512)      // 105984 (x2 CTAs)

__device__ __forceinline__ void mma_f16(float* c, const uint32_t* a,
                                        uint32_t b0, uint32_t b1) {
    asm volatile(
        "mma.sync.aligned.m16n8k16.row.col.f32.f16.f16.f32 "
        "{%0,%1,%2,%3}, {%4,%5,%6,%7}, {%8,%9}, {%0,%1,%2,%3};"
        : "+f"(c[0]), "+f"(c[1]), "+f"(c[2]), "+f"(c[3])
        : "r"(a[0]), "r"(a[1]), "r"(a[2]), "r"(a[3]), "r"(b0), "r"(b1));
}

__device__ __forceinline__ void split2h(float x, float y,
                                        uint32_t& hi, uint32_t& lo) {
    __half hx = __float2half_rn(x);
    __half hy = __float2half_rn(y);
    float lx = x - __half2float(hx);
    float ly = y - __half2float(hy);
    __half2 h = __halves2half2(hx, hy);
    __half2 l = __halves2half2(__float2half_rn(lx), __float2half_rn(ly));
    hi = *reinterpret_cast<uint32_t*>(&h);
    lo = *reinterpret_cast<uint32_t*>(&l);
}

__global__ __launch_bounds__(256, 2)
void gemm_mma_kernel(const float* __restrict__ X0,
                     const char* __restrict__ X1,     // fp16 rows, 256B/row
                     const char* __restrict__ X2,     // fp16 rows
                     const float* __restrict__ W,
                     const float* __restrict__ bias,
                     const float* __restrict__ gamma,
                     const float* __restrict__ beta,
                     float* __restrict__ out) {
    extern __shared__ char smem[];
    __shared__ int s_tile;
    int tid = threadIdx.x;
    int wid = tid >> 5, lane = tid & 31;
    int tig = lane & 3, gid = lane >> 2;

    float* sBias  = (float*)(smem + OFF_BIAS);
    float* sGamma = (float*)(smem + OFF_GAMMA);
    float* sBeta  = (float*)(smem + OFF_BETA);
    if (tid < 128) {
        sBias[tid]  = bias[tid];
        sGamma[tid] = gamma[tid];
        sBeta[tid]  = beta[tid];
    }

    for (int idx = tid; idx < 3 * 16384; idx += 256) {
        int p = idx >> 14;
        int r = idx & 16383;
        int k = r >> 7, n = r & 127;
        *(__half*)(smem + p * MAT_BYTES + ((size_t)n * KPAD + k) * 2) =
            __float2half_rn(W[idx]);
    }
    __syncthreads();

    for (;;) {
        if (tid == 0) s_tile = atomicAdd(&g_tile_ctr, 1);
        __syncthreads();
        int tile = s_tile;
        if (tile >= NT) break;
        int row0 = tile * 128;

        int r0 = row0 + wid * 16 + gid;
        bool v0 = r0 < NN, v1 = (r0 + 8) < NN;

        float cacc[16][4];
        #pragma unroll
        for (int nt = 0; nt < 16; nt++)
            #pragma unroll
            for (int j = 0; j < 4; j++) cacc[nt][j] = 0.f;

        const char* mw0 = smem;
        const char* mw1 = smem + MAT_BYTES;
        const char* mw2 = smem + 2 * MAT_BYTES;

        #pragma unroll 1
        for (int ks = 0; ks < 8; ks++) {
            int k0 = ks * 16 + tig * 2;
            // hop0: fp32 x, hi/lo split
            float2 z = make_float2(0.f, 0.f);
            float2 a00 = v0 ? *(const float2*)(X0 + (size_t)r0 * 128 + k0) : z;
            float2 a10 = v1 ? *(const float2*)(X0 + (size_t)(r0 + 8) * 128 + k0) : z;
            float2 a01 = v0 ? *(const float2*)(X0 + (size_t)r0 * 128 + k0 + 8) : z;
            float2 a11 = v1 ? *(const float2*)(X0 + (size_t)(r0 + 8) * 128 + k0 + 8) : z;
            uint32_t ahi[4], alo[4];
            split2h(a00.x, a00.y, ahi[0], alo[0]);
            split2h(a10.x, a10.y, ahi[1], alo[1]);
            split2h(a01.x, a01.y, ahi[2], alo[2]);
            split2h(a11.x, a11.y, ahi[3], alo[3]);
            // hop1/2: fp16 direct
            uint32_t a1[4], a2[4];
            size_t o0 = (size_t)r0 * 256 + k0 * 2;
            size_t o1 = (size_t)(r0 + 8) * 256 + k0 * 2;
            a1[0] = v0 ? *(const uint32_t*)(X1 + o0) : 0u;
            a1[1] = v1 ? *(const uint32_t*)(X1 + o1) : 0u;
            a1[2] = v0 ? *(const uint32_t*)(X1 + o0 + 16) : 0u;
            a1[3] = v1 ? *(const uint32_t*)(X1 + o1 + 16) : 0u;
            a2[0] = v0 ? *(const uint32_t*)(X2 + o0) : 0u;
            a2[1] = v1 ? *(const uint32_t*)(X2 + o1) : 0u;
            a2[2] = v0 ? *(const uint32_t*)(X2 + o0 + 16) : 0u;
            a2[3] = v1 ? *(const uint32_t*)(X2 + o1 + 16) : 0u;

            #pragma unroll
            for (int nt = 0; nt < 16; nt++) {
                int n = nt * 8 + gid;
                size_t boff = ((size_t)n * KPAD + k0) * 2;
                uint32_t b0 = *(const uint32_t*)(mw0 + boff);
                uint32_t b1 = *(const uint32_t*)(mw0 + boff + 16);
                mma_f16(cacc[nt], ahi, b0, b1);
                mma_f16(cacc[nt], alo, b0, b1);
                b0 = *(const uint32_t*)(mw1 + boff);
                b1 = *(const uint32_t*)(mw1 + boff + 16);
                mma_f16(cacc[nt], a1, b0, b1);
                b0 = *(const uint32_t*)(mw2 + boff);
                b1 = *(const uint32_t*)(mw2 + boff + 16);
                mma_f16(cacc[nt], a2, b0, b1);
            }
        }

        #pragma unroll
        for (int h = 0; h < 2; h++) {
            int r = r0 + h * 8;
            float s1 = 0.f, s2 = 0.f;
            #pragma unroll
            for (int nt = 0; nt < 16; nt++) {
                int col = nt * 8 + tig * 2;
                float a = cacc[nt][2 * h + 0] + sBias[col];
                float b = cacc[nt][2 * h + 1] + sBias[col + 1];
                cacc[nt][2 * h + 0] = a;
                cacc[nt][2 * h + 1] = b;
                s1 += a + b;
                s2 += a * a + b * b;
            }
            s1 += __shfl_xor_sync(0xffffffffu, s1, 1);
            s2 += __shfl_xor_sync(0xffffffffu, s2, 1);
            s1 += __shfl_xor_sync(0xffffffffu, s1, 2);
            s2 += __shfl_xor_sync(0xffffffffu, s2, 2);
            float mean = s1 * (1.f / 128.f);
            float var  = s2 * (1.f / 128.f) - mean * mean;
            float inv  = rsqrtf(var + LN_EPS);
            if (r < NN) {
                #pragma unroll
                for (int nt = 0; nt < 16; nt++) {
                    int col = nt * 8 + tig * 2;
                    float2 o;
                    o.x = fmaxf((cacc[nt][2 * h] - mean) * inv * sGamma[col]
                                + sBeta[col], 0.f);
                    o.y = fmaxf((cacc[nt][2 * h + 1] - mean) * inv * sGamma[col + 1]
                                + sBeta[col + 1], 0.f);
                    *(float2*)(out + (size_t)r * 128 + col) = o;
                }
            }
        }
        __syncthreads();
    }
}

// ================= launch =================
extern "C" void kernel_launch(void* const* d_in, const int* in_sizes, int n_in,
                              void* d_out, int out_size) {
    const float* x     = (const float*)d_in[0];
    const float* ew    = (const float*)d_in[1];
    const float* W     = (const float*)d_in[2];
    const float* bias  = (const float*)d_in[3];
    const float* gamma = (const float*)d_in[4];
    const float* beta  = (const float*)d_in[5];
    const int*   ei    = (const int*)d_in[6];
    float* out = (float*)d_out;

    uint2 *Xh, *T1h, *T2h;
    cudaGetSymbolAddress((void**)&Xh, g_xh);
    cudaGetSymbolAddress((void**)&T1h, g_t1h);
    cudaGetSymbolAddress((void**)&T2h, g_t2h);

    cudaFuncSetAttribute(gemm_mma_kernel,
                         cudaFuncAttributeMaxDynamicSharedMemorySize,
                         GEMM_SMEM);

    convert_degree_kernel<<<(NN * 32 + 255) / 256, 256>>>(x, ei, ew);
    scan_reduce_kernel<<<SCAN_BLKS, 256>>>();
    scan_partials_kernel<<<1, 256>>>();
    scan_apply_kernel<<<SCAN_BLKS, 256>>>();
    scatter_kernel<<<(EE + 255) / 256, 256>>>(ei, ew);

    // T1h = L xh ;  T2h = 2 L T1h - xh
    spmm_kernel<<<(NN * 32 + 255) / 256, 256>>>(Xh, T1h, nullptr, 1.0f);
    spmm_kernel<<<(NN * 32 + 255) / 256, 256>>>(T1h, T2h, Xh, 2.0f);

    gemm_mma_kernel<<<296, 256, GEMM_SMEM>>>(x, (const char*)T1h,
                                             (const char*)T2h,
                                             W, bias, gamma, beta, out);
}